// round 1
// baseline (speedup 1.0000x reference)
#include <cuda_runtime.h>
#include <cub/cub.cuh>
#include <cstdint>

#define BATCH 16
#define NP    25200
#define TOPKN 2048
#define MAXDET 1000
#define NCLS  80
#define FULLM 0xffffffffu

// ---------------- scratch (static device globals; no runtime alloc) ----------------
__device__ unsigned long long g_keys[BATCH * NP];
__device__ unsigned long long g_keys_sorted[BATCH * NP];
__device__ unsigned char      g_cub_temp[1 << 24];          // 16 MB, plenty for 403K keys
__device__ float4             g_boxes[BATCH * TOPKN];       // unshifted xyxy
__device__ float4             g_shifted[BATCH * TOPKN];     // class-shifted xyxy
__device__ float              g_scores[BATCH * TOPKN];
__device__ float              g_clsf[BATCH * TOPKN];
__device__ unsigned long long g_mask[(size_t)BATCH * TOPKN * 32]; // 8 MB suppression bitmask

// ---------------- stage 1: per-item score/class, pack sort key ----------------
// one warp per item; 85 floats coalesced across lanes
__global__ void k_score(const float* __restrict__ pred,
                        unsigned long long* __restrict__ keys) {
    int gw   = (blockIdx.x * blockDim.x + threadIdx.x) >> 5;
    int lane = threadIdx.x & 31;
    if (gw >= BATCH * NP) return;
    const float* p = pred + (size_t)gw * 85;

    float v0 = p[lane];
    float v1 = p[lane + 32];
    float v2 = (lane < 21) ? p[lane + 64] : -1.0f;
    float obj = __shfl_sync(FULLM, v0, 4);

    // per-lane best (max value, lowest index) among class slots 5..84
    float bv = (lane >= 5) ? v0 : -1.0f;
    int   bi = lane;
    if (v1 > bv) { bv = v1; bi = lane + 32; }
    if (v2 > bv) { bv = v2; bi = lane + 64; }
    // warp reduce with (v>, tie: lower idx)
    #pragma unroll
    for (int off = 16; off; off >>= 1) {
        float ov = __shfl_down_sync(FULLM, bv, off);
        int   oi = __shfl_down_sync(FULLM, bi, off);
        if (ov > bv || (ov == bv && oi < bi)) { bv = ov; bi = oi; }
    }
    if (lane == 0) {
        float score = __fmul_rn(obj, bv);
        bool  valid = (obj > 0.25f) && (score > 0.25f);
        float s = valid ? score : 0.0f;
        unsigned su  = __float_as_uint(s);           // s in [0,1) -> <= 0x3F800000
        unsigned inv = 0x3F800000u - su;             // ascending inv == descending score
        int b = gw / NP;
        int i = gw - b * NP;
        int cls = bi - 5;
        keys[gw] = (unsigned long long)i
                 | ((unsigned long long)inv << 15)
                 | ((unsigned long long)b   << 45)
                 | ((unsigned long long)cls << 49);  // cls above sort bits (free ride)
    }
}

// ---------------- stage 3: gather top-2048 per batch ----------------
__global__ void k_gather(const float* __restrict__ pred,
                         const unsigned long long* __restrict__ keys_sorted) {
    int t = blockIdx.x * blockDim.x + threadIdx.x;
    if (t >= BATCH * TOPKN) return;
    int b = t / TOPKN;
    int r = t - b * TOPKN;
    unsigned long long key = keys_sorted[(size_t)b * NP + r];
    int      idx = (int)(key & 0x7FFFull);
    unsigned inv = (unsigned)((key >> 15) & 0x3FFFFFFFull);
    int      cls = (int)((key >> 49) & 0x7Full);
    float s = __uint_as_float(0x3F800000u - inv);    // bit-exact masked score

    const float* p = pred + ((size_t)b * NP + idx) * 85;
    float cx = p[0], cy = p[1], w = p[2], h = p[3];
    float x1 = __fsub_rn(cx, __fmul_rn(w, 0.5f));
    float y1 = __fsub_rn(cy, __fmul_rn(h, 0.5f));
    float x2 = __fadd_rn(cx, __fmul_rn(w, 0.5f));
    float y2 = __fadd_rn(cy, __fmul_rn(h, 0.5f));
    float c  = __fmul_rn((float)cls, 4096.0f);       // exact

    g_boxes[t]   = make_float4(x1, y1, x2, y2);
    g_shifted[t] = make_float4(__fadd_rn(x1, c), __fadd_rn(y1, c),
                               __fadd_rn(x2, c), __fadd_rn(y2, c));
    g_scores[t]  = s;
    g_clsf[t]    = (float)cls;
}

// ---------------- stage 4: 2048x2048 suppression bitmask (j > i only) ----------------
__global__ void k_mask() {
    __shared__ float4 cbox[64];
    __shared__ float  carea[64];
    int cb = blockIdx.x, rb = blockIdx.y, b = blockIdx.z;
    int tid = threadIdx.x;
    unsigned long long bits = 0ull;

    if (cb >= rb) {
        float4 q = g_shifted[(size_t)b * TOPKN + cb * 64 + tid];
        cbox[tid]  = q;
        carea[tid] = __fmul_rn(__fsub_rn(q.z, q.x), __fsub_rn(q.w, q.y));
        __syncthreads();

        int row = rb * 64 + tid;
        float4 a = g_shifted[(size_t)b * TOPKN + row];
        float areaA = __fmul_rn(__fsub_rn(a.z, a.x), __fsub_rn(a.w, a.y));

        #pragma unroll 8
        for (int j = 0; j < 64; j++) {
            int jg = cb * 64 + j;
            if (jg > row) {
                float4 q2 = cbox[j];
                float ltx = fmaxf(a.x, q2.x);
                float lty = fmaxf(a.y, q2.y);
                float rbx = fminf(a.z, q2.z);
                float rby = fminf(a.w, q2.w);
                float ww = fmaxf(__fsub_rn(rbx, ltx), 0.0f);
                float hh = fmaxf(__fsub_rn(rby, lty), 0.0f);
                float inter = __fmul_rn(ww, hh);
                // ((areaA + areaB) - inter) + 1e-7  -- exact reference order
                float denom = __fadd_rn(__fsub_rn(__fadd_rn(areaA, carea[j]), inter), 1e-7f);
                float iou = __fdiv_rn(inter, denom);
                if (iou > 0.45f) bits |= (1ull << j);
            }
        }
    }
    g_mask[((size_t)b * TOPKN + rb * 64 + tid) * 32 + cb] = bits;
}

// ---------------- stage 5: serial greedy pass + compact output ----------------
// one warp per batch; lane L owns the 64-bit removed/keep word for candidates [64L, 64L+64)
__global__ void k_final(float* __restrict__ out) {
    __shared__ unsigned long long sh_col[64];
    int b    = blockIdx.x;
    int lane = threadIdx.x;

    // validity bits (tops > 0)
    unsigned long long valid = 0ull;
    {
        const float* sp = &g_scores[(size_t)b * TOPKN + lane * 64];
        #pragma unroll 8
        for (int k = 0; k < 64; k++)
            if (sp[k] > 0.0f) valid |= (1ull << k);
    }

    unsigned long long removed = 0ull, keep = 0ull;

    for (int w = 0; w < 32; ++w) {
        // prefetch column-w slice of the 64 rows in word w
        sh_col[lane]      = g_mask[((size_t)b * TOPKN + w * 64 + lane)      * 32 + w];
        sh_col[lane + 32] = g_mask[((size_t)b * TOPKN + w * 64 + lane + 32) * 32 + w];
        __syncwarp();

        unsigned long long rw = __shfl_sync(FULLM, removed, w);
        unsigned long long vw = __shfl_sync(FULLM, valid,   w);
        unsigned long long proc = 0ull;

        // serial alive/suppress chain, register+shared only (all lanes redundantly)
        #pragma unroll
        for (int k = 0; k < 64; k++) {
            unsigned long long cr = sh_col[k];
            bool alive = (((vw & ~rw) >> k) & 1ull) != 0ull;
            rw   |= alive ? cr : 0ull;
            proc |= alive ? (1ull << k) : 0ull;
        }
        if (lane == w) keep = proc;

        // apply full rows of the alive set to all lanes' removed words
        const unsigned long long* rowbase =
            &g_mask[((size_t)b * TOPKN + w * 64) * 32 + lane];
        #pragma unroll 8
        for (int k = 0; k < 64; k++) {
            unsigned long long v = rowbase[(size_t)k * 32];  // unconditional -> high MLP
            if ((proc >> k) & 1ull) removed |= v;
        }
        __syncwarp();
    }

    // compact survivors in sorted order (== reference's final top_k of masked tops)
    unsigned cnt  = __popcll(keep);
    unsigned incl = cnt;
    #pragma unroll
    for (int d = 1; d < 32; d <<= 1) {
        unsigned n = __shfl_up_sync(FULLM, incl, d);
        if (lane >= d) incl += n;
    }
    unsigned total = __shfl_sync(FULLM, incl, 31);
    unsigned rank  = incl - cnt;

    unsigned long long kk = keep;
    while (kk) {
        int bit = __ffsll((long long)kk) - 1;
        kk &= kk - 1;
        if (rank < MAXDET) {
            int r = lane * 64 + bit;
            float4 bx = g_boxes[(size_t)b * TOPKN + r];
            float* o = out + ((size_t)b * MAXDET + rank) * 6;
            o[0] = bx.x; o[1] = bx.y; o[2] = bx.z; o[3] = bx.w;
            o[4] = g_scores[(size_t)b * TOPKN + r];
            o[5] = g_clsf[(size_t)b * TOPKN + r];
        }
        rank++;
    }
    unsigned fillstart = total < MAXDET ? total : MAXDET;
    for (unsigned m = fillstart + lane; m < MAXDET; m += 32) {
        float* o = out + ((size_t)b * MAXDET + m) * 6;
        o[0] = 0.f; o[1] = 0.f; o[2] = 0.f; o[3] = 0.f; o[4] = 0.f; o[5] = -1.f;
    }
}

// ---------------- launch ----------------
extern "C" void kernel_launch(void* const* d_in, const int* in_sizes, int n_in,
                              void* d_out, int out_size) {
    (void)in_sizes; (void)n_in; (void)out_size;
    const float* pred = (const float*)d_in[0];
    float* out = (float*)d_out;

    void *keys_p, *keys_sorted_p, *temp_p;
    cudaGetSymbolAddress(&keys_p, g_keys);
    cudaGetSymbolAddress(&keys_sorted_p, g_keys_sorted);
    cudaGetSymbolAddress(&temp_p, g_cub_temp);

    size_t temp_bytes = 0;
    cub::DeviceRadixSort::SortKeys(nullptr, temp_bytes,
        (const unsigned long long*)keys_p, (unsigned long long*)keys_sorted_p,
        BATCH * NP, 0, 49);
    if (temp_bytes > sizeof(g_cub_temp)) return;  // would indicate config bug

    {   // stage 1
        int warps = BATCH * NP;
        int threads = 256;
        int blocks = (warps * 32 + threads - 1) / threads;
        k_score<<<blocks, threads>>>(pred, (unsigned long long*)keys_p);
    }
    // stage 2: one global radix sort over packed keys (bits [0,49))
    cub::DeviceRadixSort::SortKeys(temp_p, temp_bytes,
        (const unsigned long long*)keys_p, (unsigned long long*)keys_sorted_p,
        BATCH * NP, 0, 49, (cudaStream_t)0);

    {   // stage 3
        int n = BATCH * TOPKN;
        k_gather<<<(n + 255) / 256, 256>>>(pred, (const unsigned long long*)keys_sorted_p);
    }
    // stage 4
    k_mask<<<dim3(32, 32, BATCH), 64>>>();
    // stage 5
    k_final<<<BATCH, 32>>>(out);
}

// round 2
// speedup vs baseline: 1.4213x; 1.4213x over previous
#include <cuda_runtime.h>
#include <cub/cub.cuh>
#include <cstdint>

#define BATCH  16
#define NP     25200
#define TOPKN  2048
#define MAXDET 1000
#define CANDN  3072
#define SORT_THREADS 512
#define SORT_ITEMS   6
#define FULLM  0xffffffffu
typedef unsigned long long u64;

// ---------------- scratch (static device globals; zero-init at load) ----------------
__device__ u64    g_keys[BATCH * NP];          // idx(15) | inv(25)<<15 | cls(7)<<40
__device__ int    g_hist[BATCH * 132];         // bucket = inv>>17 (valid only); reset by k_final
__device__ int    g_cnt[BATCH];                // compact counters; reset by k_final
__device__ int    g_cut[BATCH];
__device__ u64    g_cand[BATCH * CANDN];
__device__ float4 g_boxes[BATCH * TOPKN];
__device__ float4 g_shifted[BATCH * TOPKN];
__device__ float  g_scores[BATCH * TOPKN];
__device__ float  g_clsf[BATCH * TOPKN];
__device__ u64    g_mask[(size_t)BATCH * TOPKN * 32];  // only upper off-diag words written/read
__device__ u64    g_diag[BATCH * 32 * 64];             // diagonal 64x64 blocks, contiguous

// ---------------- stage 1: score/class, pack key, bucket histogram ----------------
__global__ void k_score(const float* __restrict__ pred, u64* __restrict__ keys) {
    int gw   = (blockIdx.x * blockDim.x + threadIdx.x) >> 5;
    int lane = threadIdx.x & 31;
    if (gw >= BATCH * NP) return;
    const float* p = pred + (size_t)gw * 85;

    float v0 = p[lane];
    float v1 = p[lane + 32];
    float v2 = (lane < 21) ? p[lane + 64] : -1.0f;
    float obj = __shfl_sync(FULLM, v0, 4);

    float bv = (lane >= 5) ? v0 : -1.0f;
    int   bi = lane;
    if (v1 > bv) { bv = v1; bi = lane + 32; }
    if (v2 > bv) { bv = v2; bi = lane + 64; }
    #pragma unroll
    for (int off = 16; off; off >>= 1) {
        float ov = __shfl_down_sync(FULLM, bv, off);
        int   oi = __shfl_down_sync(FULLM, bi, off);
        if (ov > bv || (ov == bv && oi < bi)) { bv = ov; bi = oi; }
    }
    if (lane == 0) {
        float score = __fmul_rn(obj, bv);
        bool  valid = (obj > 0.25f) && (score > 0.25f);
        int b = gw / NP;
        int i = gw - b * NP;
        int cls = bi - 5;
        unsigned inv;
        if (valid) {
            inv = 0x3F800000u - __float_as_uint(score);   // < 0x1000000 for score > 0.25
            atomicAdd(&g_hist[b * 132 + (inv >> 17)], 1);
        } else {
            inv = 0x1000000u;                             // sentinel: sorts after all valid
        }
        keys[gw] = (u64)i | ((u64)inv << 15) | ((u64)cls << 40);
    }
}

// ---------------- stage 2a: per-batch cutoff bucket ----------------
__global__ void k_cutoff() {
    int b = blockIdx.x;
    if (threadIdx.x == 0) {
        int cum = 0, c = 128;                 // 128 => include everything (incl. invalid)
        for (int i = 0; i < 128; i++) {
            cum += g_hist[b * 132 + i];
            if (cum >= TOPKN) { c = i; break; }
        }
        g_cut[b] = c;
    }
}

// ---------------- stage 2b: compact candidates above cutoff ----------------
__global__ void k_compact() {
    int t = blockIdx.x * blockDim.x + threadIdx.x;
    if (t >= BATCH * NP) return;
    int b = t / NP;
    u64 key = g_keys[t];
    unsigned inv = (unsigned)((key >> 15) & 0x1FFFFFFull);
    if ((int)(inv >> 17) <= g_cut[b]) {
        int pos = atomicAdd(&g_cnt[b], 1);
        if (pos < CANDN) g_cand[b * CANDN + pos] = key;
    }
}

// ---------------- stage 3: per-batch block sort + gather (fused) ----------------
__global__ void __launch_bounds__(SORT_THREADS)
k_sortgather(const float* __restrict__ pred) {
    typedef cub::BlockRadixSort<u64, SORT_THREADS, SORT_ITEMS> BRS;
    __shared__ typename BRS::TempStorage ts;
    int b = blockIdx.x, t = threadIdx.x;
    int M = min(g_cnt[b], CANDN);

    u64 keys[SORT_ITEMS];
    #pragma unroll
    for (int i = 0; i < SORT_ITEMS; i++) {
        int r = t * SORT_ITEMS + i;
        keys[i] = (r < M) ? g_cand[b * CANDN + r] : ~0ull;
    }
    BRS(ts).Sort(keys, 0, 40);   // ascending (inv, idx) == score desc, stable by index

    #pragma unroll
    for (int i = 0; i < SORT_ITEMS; i++) {
        int r = t * SORT_ITEMS + i;
        if (r >= TOPKN) continue;
        int g = b * TOPKN + r;
        u64 key = keys[i];
        if (key == ~0ull) {  // padding sentinel: no real item
            g_boxes[g]   = make_float4(0.f, 0.f, 0.f, 0.f);
            g_shifted[g] = make_float4(0.f, 0.f, 0.f, 0.f);
            g_scores[g]  = 0.f;
            g_clsf[g]    = 0.f;
            continue;
        }
        int      idx = (int)(key & 0x7FFFull);
        unsigned inv = (unsigned)((key >> 15) & 0x1FFFFFFull);
        int      cls = (int)((key >> 40) & 0x7Full);
        float s = (inv >= 0x1000000u) ? 0.0f : __uint_as_float(0x3F800000u - inv);

        const float* p = pred + ((size_t)b * NP + idx) * 85;
        float cx = p[0], cy = p[1], w = p[2], h = p[3];
        float x1 = __fsub_rn(cx, __fmul_rn(w, 0.5f));
        float y1 = __fsub_rn(cy, __fmul_rn(h, 0.5f));
        float x2 = __fadd_rn(cx, __fmul_rn(w, 0.5f));
        float y2 = __fadd_rn(cy, __fmul_rn(h, 0.5f));
        float c  = __fmul_rn((float)cls, 4096.0f);

        g_boxes[g]   = make_float4(x1, y1, x2, y2);
        g_shifted[g] = make_float4(__fadd_rn(x1, c), __fadd_rn(y1, c),
                                   __fadd_rn(x2, c), __fadd_rn(y2, c));
        g_scores[g]  = s;
        g_clsf[g]    = (float)cls;
    }
}

// ---------------- stage 4: suppression bitmask, upper triangle only ----------------
__global__ void k_mask() {
    __shared__ float4 cbox[64];
    __shared__ float  carea[64];
    // map linear triangle index -> (rb, cb), cb >= rb
    int tI = blockIdx.x, rb = 0, rem = 32;
    while (tI >= rem) { tI -= rem; rb++; rem--; }
    int cb = rb + tI;
    int b = blockIdx.y;
    int tid = threadIdx.x;

    float4 q = g_shifted[(size_t)b * TOPKN + cb * 64 + tid];
    cbox[tid]  = q;
    carea[tid] = __fmul_rn(__fsub_rn(q.z, q.x), __fsub_rn(q.w, q.y));
    __syncthreads();

    int row = rb * 64 + tid;
    float4 a = g_shifted[(size_t)b * TOPKN + row];
    float areaA = __fmul_rn(__fsub_rn(a.z, a.x), __fsub_rn(a.w, a.y));

    u64 bits = 0ull;
    #pragma unroll 8
    for (int j = 0; j < 64; j++) {
        int jg = cb * 64 + j;
        if (jg > row) {
            float4 q2 = cbox[j];
            float ltx = fmaxf(a.x, q2.x);
            float lty = fmaxf(a.y, q2.y);
            float rbx = fminf(a.z, q2.z);
            float rby = fminf(a.w, q2.w);
            float ww = fmaxf(__fsub_rn(rbx, ltx), 0.0f);
            float hh = fmaxf(__fsub_rn(rby, lty), 0.0f);
            float inter = __fmul_rn(ww, hh);
            float denom = __fadd_rn(__fsub_rn(__fadd_rn(areaA, carea[j]), inter), 1e-7f);
            float iou = __fdiv_rn(inter, denom);
            if (iou > 0.45f) bits |= (1ull << j);
        }
    }
    if (cb == rb) g_diag[(b * 32 + rb) * 64 + tid] = bits;
    else          g_mask[((size_t)b * TOPKN + rb * 64 + tid) * 32 + cb] = bits;
}

// ---------------- stage 5: greedy pass (256 thr/batch) + compact output ----------------
__global__ void __launch_bounds__(256) k_final(float* __restrict__ out) {
    __shared__ u64 s_col[64];
    __shared__ u64 s_valid[32], s_keep[32], s_removed[32];
    __shared__ u64 s_proc;
    __shared__ unsigned s_total;
    int b = blockIdx.x, t = threadIdx.x;
    int lane = t & 31, wid = t >> 5;

    if (t < 32) {
        u64 v = 0ull;
        const float* sp = &g_scores[(size_t)b * TOPKN + t * 64];
        #pragma unroll 8
        for (int k = 0; k < 64; k++)
            if (sp[k] > 0.0f) v |= (1ull << k);
        s_valid[t] = v; s_removed[t] = 0ull; s_keep[t] = 0ull;
    }
    __syncthreads();

    for (int w = 0; w < 32; ++w) {
        if (t < 64) s_col[t] = g_diag[(b * 32 + w) * 64 + t];

        // issue row loads for the apply step BEFORE the chain (latency overlap)
        u64 rv[8];
        #pragma unroll
        for (int rr = 0; rr < 8; rr++) {
            int k = rr * 8 + wid;
            rv[rr] = (lane > w)
                ? g_mask[((size_t)b * TOPKN + w * 64 + k) * 32 + lane] : 0ull;
        }
        __syncthreads();

        if (wid == 0) {
            u64 vw = s_valid[w], rw = s_removed[w];
            u64 c0 = s_col[lane], c1 = s_col[lane + 32];
            unsigned nz0 = __ballot_sync(FULLM, c0 != 0ull);
            unsigned nz1 = __ballot_sync(FULLM, c1 != 0ull);
            u64 m = (((u64)nz1 << 32) | (u64)nz0) & vw;   // only valid items can suppress
            while (m) {  // serial chain over *nonzero* suppressor columns only
                int k = __ffsll((long long)m) - 1;
                m &= m - 1;
                if (((vw & ~rw) >> k) & 1ull) rw |= s_col[k];
            }
            // row i's word-w bits only cover j>i, so bit k of rw is final by step k:
            u64 proc = vw & ~rw;
            if (lane == 0) { s_keep[w] = proc; s_proc = proc; }
        }
        __syncthreads();

        u64 proc = s_proc;
        u64 acc = 0ull;
        #pragma unroll
        for (int rr = 0; rr < 8; rr++) {
            int k = rr * 8 + wid;
            if ((proc >> k) & 1ull) acc |= rv[rr];
        }
        if (acc) atomicOr(&s_removed[lane], acc);
        __syncthreads();
    }

    // compact survivors in sorted order (warp 0)
    if (wid == 0) {
        u64 keep = s_keep[lane];
        unsigned cnt = __popcll(keep), incl = cnt;
        #pragma unroll
        for (int d = 1; d < 32; d <<= 1) {
            unsigned n = __shfl_up_sync(FULLM, incl, d);
            if (lane >= d) incl += n;
        }
        unsigned total = __shfl_sync(FULLM, incl, 31);
        unsigned rank = incl - cnt;
        u64 kk = keep;
        while (kk) {
            int bit = __ffsll((long long)kk) - 1;
            kk &= kk - 1;
            if (rank < MAXDET) {
                int r = lane * 64 + bit;
                float4 bx = g_boxes[(size_t)b * TOPKN + r];
                float* o = out + ((size_t)b * MAXDET + rank) * 6;
                o[0] = bx.x; o[1] = bx.y; o[2] = bx.z; o[3] = bx.w;
                o[4] = g_scores[(size_t)b * TOPKN + r];
                o[5] = g_clsf[(size_t)b * TOPKN + r];
            }
            rank++;
        }
        if (lane == 0) s_total = total;
    }
    __syncthreads();

    unsigned fillstart = min(s_total, (unsigned)MAXDET);
    for (unsigned m = fillstart + t; m < MAXDET; m += 256) {
        float* o = out + ((size_t)b * MAXDET + m) * 6;
        o[0] = 0.f; o[1] = 0.f; o[2] = 0.f; o[3] = 0.f; o[4] = 0.f; o[5] = -1.f;
    }

    // reset per-run counters for the next graph replay
    if (t < 132) g_hist[b * 132 + t] = 0;
    if (t == 0)  g_cnt[b] = 0;
}

// ---------------- launch ----------------
extern "C" void kernel_launch(void* const* d_in, const int* in_sizes, int n_in,
                              void* d_out, int out_size) {
    (void)in_sizes; (void)n_in; (void)out_size;
    const float* pred = (const float*)d_in[0];
    float* out = (float*)d_out;

    void* keys_p;
    cudaGetSymbolAddress(&keys_p, g_keys);

    {   // stage 1
        int warps = BATCH * NP;
        int threads = 256;
        int blocks = (warps * 32 + threads - 1) / threads;
        k_score<<<blocks, threads>>>(pred, (u64*)keys_p);
    }
    k_cutoff<<<BATCH, 32>>>();
    {   // stage 2b
        int n = BATCH * NP;
        k_compact<<<(n + 255) / 256, 256>>>();
    }
    k_sortgather<<<BATCH, SORT_THREADS>>>(pred);
    k_mask<<<dim3(528, BATCH), 64>>>();
    k_final<<<BATCH, 256>>>(out);
}

// round 3
// speedup vs baseline: 1.8230x; 1.2826x over previous
#include <cuda_runtime.h>
#include <cub/cub.cuh>
#include <cstdint>

#define BATCH  16
#define NP     25200
#define TOPKN  2048
#define MAXDET 1000
#define CANDN  3072
#define SC_THREADS 1024
#define SC_ITEMS   3
#define FULLM  0xffffffffu
typedef unsigned long long u64;

// ---------------- scratch (static device globals) ----------------
__device__ u64    g_keys[BATCH * NP];          // idx(15) | inv(25)<<15 | cls(7)<<40
__device__ int    g_hist[BATCH * 132];         // bucket = inv>>17 (valid only); reset in k_sortcompact
__device__ float4 g_boxes[BATCH * TOPKN];
__device__ float4 g_shifted[BATCH * TOPKN];
__device__ float  g_scores[BATCH * TOPKN];
__device__ float  g_clsf[BATCH * TOPKN];
__device__ u64    g_mask[(size_t)BATCH * TOPKN * 32];  // upper off-diag words only
__device__ u64    g_diag[BATCH * 32 * 64];             // diagonal 64x64 blocks

// ---------------- stage 1: score/class, pack key, bucket histogram ----------------
__global__ void k_score(const float* __restrict__ pred, u64* __restrict__ keys) {
    int gw   = (blockIdx.x * blockDim.x + threadIdx.x) >> 5;
    int lane = threadIdx.x & 31;
    if (gw >= BATCH * NP) return;
    const float* p = pred + (size_t)gw * 85;

    float v0 = p[lane];
    float v1 = p[lane + 32];
    float v2 = (lane < 21) ? p[lane + 64] : -1.0f;
    float obj = __shfl_sync(FULLM, v0, 4);

    float bv = (lane >= 5) ? v0 : -1.0f;
    int   bi = lane;
    if (v1 > bv) { bv = v1; bi = lane + 32; }
    if (v2 > bv) { bv = v2; bi = lane + 64; }
    #pragma unroll
    for (int off = 16; off; off >>= 1) {
        float ov = __shfl_down_sync(FULLM, bv, off);
        int   oi = __shfl_down_sync(FULLM, bi, off);
        if (ov > bv || (ov == bv && oi < bi)) { bv = ov; bi = oi; }
    }
    if (lane == 0) {
        float score = __fmul_rn(obj, bv);
        bool  valid = (obj > 0.25f) && (score > 0.25f);
        int b = gw / NP;
        int i = gw - b * NP;
        int cls = bi - 5;
        unsigned inv;
        if (valid) {
            inv = 0x3F800000u - __float_as_uint(score);   // < 0x1000000 when score > 0.25
            atomicAdd(&g_hist[b * 132 + (inv >> 17)], 1);
        } else {
            inv = 0x1000000u;                             // invalid marker
        }
        keys[gw] = (u64)i | ((u64)inv << 15) | ((u64)cls << 40);
    }
}

// ---------------- stage 2: cutoff + ordered compact + 25-bit stable sort + gather ----------------
__global__ void __launch_bounds__(SC_THREADS)
k_sortcompact(const float* __restrict__ pred) {
    typedef cub::BlockRadixSort<unsigned, SC_THREADS, SC_ITEMS, unsigned> BRS;
    __shared__ union {
        struct { unsigned ck[CANDN]; unsigned cv[CANDN]; } c;
        typename BRS::TempStorage sort;
    } u;
    __shared__ int s_wcnt[32], s_woff[32];
    __shared__ int s_base, s_agg, s_cut;
    __shared__ int s_hist[128];

    int b = blockIdx.x, t = threadIdx.x;
    int lane = t & 31, wid = t >> 5;

    if (t < 128) { s_hist[t] = g_hist[b * 132 + t]; g_hist[b * 132 + t] = 0; }
    if (t == 0) s_base = 0;
    __syncthreads();
    if (t == 0) {
        int cum = 0, c = 128;
        for (int i = 0; i < 128; i++) {
            cum += s_hist[i];
            if (cum >= TOPKN) { c = i; break; }
        }
        s_cut = c;
    }
    __syncthreads();
    int cut = s_cut;

    // ordered (idx-ascending) compaction of valid candidates above the cutoff bucket
    for (int r = 0; r < (NP + SC_THREADS - 1) / SC_THREADS; r++) {
        int i = r * SC_THREADS + t;
        u64 key = 0; unsigned inv = 0xFFFFFFFFu;
        bool flag = false;
        if (i < NP) {
            key = g_keys[(size_t)b * NP + i];
            inv = (unsigned)((key >> 15) & 0x1FFFFFFull);
            flag = (inv < 0x1000000u) && ((int)(inv >> 17) <= cut);
        }
        unsigned bal = __ballot_sync(FULLM, flag);
        if (lane == 0) s_wcnt[wid] = __popc(bal);
        __syncthreads();
        if (t < 32) {
            int v = s_wcnt[t], incl = v;
            #pragma unroll
            for (int d = 1; d < 32; d <<= 1) {
                int n = __shfl_up_sync(FULLM, incl, d);
                if (t >= d) incl += n;
            }
            s_woff[t] = incl - v;
            if (t == 31) s_agg = incl;
        }
        __syncthreads();
        if (flag) {
            int pos = s_base + s_woff[wid] + __popc(bal & ((1u << lane) - 1));
            if (pos < CANDN) {
                u.c.ck[pos] = inv;
                u.c.cv[pos] = (unsigned)(key & 0x7FFFull) |
                              ((unsigned)((key >> 40) & 0x7Full) << 16);
            }
        }
        __syncthreads();
        if (t == 0) s_base += s_agg;
    }
    __syncthreads();
    int M = min(s_base, CANDN);

    unsigned keys[SC_ITEMS], vals[SC_ITEMS];
    #pragma unroll
    for (int i = 0; i < SC_ITEMS; i++) {
        int r = t * SC_ITEMS + i;
        keys[i] = (r < M) ? u.c.ck[r] : 0x1FFFFFFu;   // padding sorts last
        vals[i] = (r < M) ? u.c.cv[r] : 0u;
    }
    __syncthreads();
    // stable ascending sort on 25-bit inv; idx-order compaction supplies the tie-break
    BRS(u.sort).Sort(keys, vals, 0, 25);

    #pragma unroll
    for (int i = 0; i < SC_ITEMS; i++) {
        int r = t * SC_ITEMS + i;
        if (r >= TOPKN) continue;
        int g = b * TOPKN + r;
        unsigned inv = keys[i];
        if (inv >= 0x1000000u) {    // padding: no real candidate at this rank
            g_boxes[g]   = make_float4(0.f, 0.f, 0.f, 0.f);
            g_shifted[g] = make_float4(0.f, 0.f, 0.f, 0.f);
            g_scores[g]  = 0.f;
            g_clsf[g]    = 0.f;
            continue;
        }
        int idx = (int)(vals[i] & 0xFFFFu);
        int cls = (int)(vals[i] >> 16);
        float s = __uint_as_float(0x3F800000u - inv);

        const float* p = pred + ((size_t)b * NP + idx) * 85;
        float cx = p[0], cy = p[1], w = p[2], h = p[3];
        float x1 = __fsub_rn(cx, __fmul_rn(w, 0.5f));
        float y1 = __fsub_rn(cy, __fmul_rn(h, 0.5f));
        float x2 = __fadd_rn(cx, __fmul_rn(w, 0.5f));
        float y2 = __fadd_rn(cy, __fmul_rn(h, 0.5f));
        float c  = __fmul_rn((float)cls, 4096.0f);

        g_boxes[g]   = make_float4(x1, y1, x2, y2);
        g_shifted[g] = make_float4(__fadd_rn(x1, c), __fadd_rn(y1, c),
                                   __fadd_rn(x2, c), __fadd_rn(y2, c));
        g_scores[g]  = s;
        g_clsf[g]    = (float)cls;
    }
}

// ---------------- stage 3: suppression bitmask, upper triangle, division-free fast path ----------------
__global__ void k_mask() {
    __shared__ float4 cbox[64];
    __shared__ float  carea[64];
    int tI = blockIdx.x, rb = 0, rem = 32;
    while (tI >= rem) { tI -= rem; rb++; rem--; }
    int cb = rb + tI;
    int b = blockIdx.y;
    int tid = threadIdx.x;

    float4 q = g_shifted[(size_t)b * TOPKN + cb * 64 + tid];
    cbox[tid]  = q;
    carea[tid] = __fmul_rn(__fsub_rn(q.z, q.x), __fsub_rn(q.w, q.y));
    __syncthreads();

    int row = rb * 64 + tid;
    float4 a = g_shifted[(size_t)b * TOPKN + row];
    float areaA = __fmul_rn(__fsub_rn(a.z, a.x), __fsub_rn(a.w, a.y));

    u64 bits = 0ull;
    #pragma unroll 8
    for (int j = 0; j < 64; j++) {
        int jg = cb * 64 + j;
        float4 q2 = cbox[j];
        float ltx = fmaxf(a.x, q2.x);
        float lty = fmaxf(a.y, q2.y);
        float rbx = fminf(a.z, q2.z);
        float rby = fminf(a.w, q2.w);
        float ww = fmaxf(__fsub_rn(rbx, ltx), 0.0f);
        float hh = fmaxf(__fsub_rn(rby, lty), 0.0f);
        float inter = __fmul_rn(ww, hh);
        if (jg > row && inter > 0.0f) {
            float denom = __fadd_rn(__fsub_rn(__fadd_rn(areaA, carea[j]), inter), 1e-7f);
            bool bit;
            if (inter > __fmul_rn(0.4501f, denom))      bit = true;   // certainly > 0.45
            else if (inter <= __fmul_rn(0.4499f, denom)) bit = false; // certainly <= 0.45
            else bit = (__fdiv_rn(inter, denom) > 0.45f);             // exact on the boundary band
            if (bit) bits |= (1ull << j);
        }
    }
    if (cb == rb) g_diag[(b * 32 + rb) * 64 + tid] = bits;
    else          g_mask[((size_t)b * TOPKN + rb * 64 + tid) * 32 + cb] = bits;
}

// ---------------- stage 4: greedy pass + compact output ----------------
__global__ void __launch_bounds__(256) k_final(float* __restrict__ out) {
    __shared__ u64 s_col[64];
    __shared__ u64 s_valid[32], s_keep[32], s_removed[32];
    __shared__ u64 s_proc;
    __shared__ unsigned s_total;
    int b = blockIdx.x, t = threadIdx.x;
    int lane = t & 31, wid = t >> 5;

    if (t < 32) {
        u64 v = 0ull;
        const float* sp = &g_scores[(size_t)b * TOPKN + t * 64];
        #pragma unroll 8
        for (int k = 0; k < 64; k++)
            if (sp[k] > 0.0f) v |= (1ull << k);
        s_valid[t] = v; s_removed[t] = 0ull; s_keep[t] = 0ull;
    }
    __syncthreads();

    for (int w = 0; w < 32; ++w) {
        if (t < 64) s_col[t] = g_diag[(b * 32 + w) * 64 + t];

        u64 rv[8];
        #pragma unroll
        for (int rr = 0; rr < 8; rr++) {
            int k = rr * 8 + wid;
            rv[rr] = (lane > w)
                ? g_mask[((size_t)b * TOPKN + w * 64 + k) * 32 + lane] : 0ull;
        }
        __syncthreads();

        if (wid == 0) {
            u64 vw = s_valid[w], rw = s_removed[w];
            u64 c0 = s_col[lane], c1 = s_col[lane + 32];
            unsigned nz0 = __ballot_sync(FULLM, c0 != 0ull);
            unsigned nz1 = __ballot_sync(FULLM, c1 != 0ull);
            u64 m = (((u64)nz1 << 32) | (u64)nz0) & vw;
            while (m) {
                int k = __ffsll((long long)m) - 1;
                m &= m - 1;
                if (((vw & ~rw) >> k) & 1ull) rw |= s_col[k];
            }
            u64 proc = vw & ~rw;
            if (lane == 0) { s_keep[w] = proc; s_proc = proc; }
        }
        __syncthreads();

        u64 proc = s_proc;
        u64 acc = 0ull;
        #pragma unroll
        for (int rr = 0; rr < 8; rr++) {
            int k = rr * 8 + wid;
            if ((proc >> k) & 1ull) acc |= rv[rr];
        }
        if (acc) atomicOr(&s_removed[lane], acc);
        __syncthreads();
    }

    if (wid == 0) {
        u64 keep = s_keep[lane];
        unsigned cnt = __popcll(keep), incl = cnt;
        #pragma unroll
        for (int d = 1; d < 32; d <<= 1) {
            unsigned n = __shfl_up_sync(FULLM, incl, d);
            if (lane >= d) incl += n;
        }
        unsigned total = __shfl_sync(FULLM, incl, 31);
        unsigned rank = incl - cnt;
        u64 kk = keep;
        while (kk) {
            int bit = __ffsll((long long)kk) - 1;
            kk &= kk - 1;
            if (rank < MAXDET) {
                int r = lane * 64 + bit;
                float4 bx = g_boxes[(size_t)b * TOPKN + r];
                float* o = out + ((size_t)b * MAXDET + rank) * 6;
                o[0] = bx.x; o[1] = bx.y; o[2] = bx.z; o[3] = bx.w;
                o[4] = g_scores[(size_t)b * TOPKN + r];
                o[5] = g_clsf[(size_t)b * TOPKN + r];
            }
            rank++;
        }
        if (lane == 0) s_total = total;
    }
    __syncthreads();

    unsigned fillstart = min(s_total, (unsigned)MAXDET);
    for (unsigned m = fillstart + t; m < MAXDET; m += 256) {
        float* o = out + ((size_t)b * MAXDET + m) * 6;
        o[0] = 0.f; o[1] = 0.f; o[2] = 0.f; o[3] = 0.f; o[4] = 0.f; o[5] = -1.f;
    }
}

// ---------------- launch ----------------
extern "C" void kernel_launch(void* const* d_in, const int* in_sizes, int n_in,
                              void* d_out, int out_size) {
    (void)in_sizes; (void)n_in; (void)out_size;
    const float* pred = (const float*)d_in[0];
    float* out = (float*)d_out;

    void* keys_p;
    cudaGetSymbolAddress(&keys_p, g_keys);

    {   // stage 1
        int warps = BATCH * NP;
        int threads = 256;
        int blocks = (warps * 32 + threads - 1) / threads;
        k_score<<<blocks, threads>>>(pred, (u64*)keys_p);
    }
    k_sortcompact<<<BATCH, SC_THREADS>>>(pred);
    k_mask<<<dim3(528, BATCH), 64>>>();
    k_final<<<BATCH, 256>>>(out);
}

// round 4
// speedup vs baseline: 2.1261x; 1.1663x over previous
#include <cuda_runtime.h>
#include <cub/cub.cuh>
#include <cstdint>

#define BATCH  16
#define NP     25200
#define TOPKN  2048
#define MAXDET 1000
#define CANDN  3072
#define SC_THREADS 1024
#define SC_ITEMS   3
#define FULLM  0xffffffffu
typedef unsigned long long u64;

// ---------------- scratch (static device globals) ----------------
__device__ u64      g_keys[BATCH * NP];        // idx(15) | inv(25)<<15 | cls(7)<<40
__device__ int      g_hist[BATCH * 132];       // bucket = inv>>17 (valid only); reset in k_sortcompact
__device__ float4   g_boxes[BATCH * TOPKN];
__device__ float4   g_shifted[BATCH * TOPKN];
__device__ float    g_scores[BATCH * TOPKN];
__device__ float    g_clsf[BATCH * TOPKN];
__device__ u64      g_mask[(size_t)BATCH * TOPKN * 32]; // upper off-diag words only
__device__ u64      g_diag[BATCH * 32 * 64];            // diagonal 64x64 blocks
__device__ unsigned g_nzflag[BATCH * TOPKN];            // bit cb set if row's word cb nonzero

// ---------------- stage 1: score/class, pack key, bucket histogram ----------------
__global__ void k_score(const float* __restrict__ pred, u64* __restrict__ keys) {
    int gw   = (blockIdx.x * blockDim.x + threadIdx.x) >> 5;
    int lane = threadIdx.x & 31;
    if (gw >= BATCH * NP) return;
    const float* p = pred + (size_t)gw * 85;

    float v0 = p[lane];
    float v1 = p[lane + 32];
    float v2 = (lane < 21) ? p[lane + 64] : -1.0f;
    float obj = __shfl_sync(FULLM, v0, 4);

    float bv = (lane >= 5) ? v0 : -1.0f;
    int   bi = lane;
    if (v1 > bv) { bv = v1; bi = lane + 32; }
    if (v2 > bv) { bv = v2; bi = lane + 64; }
    #pragma unroll
    for (int off = 16; off; off >>= 1) {
        float ov = __shfl_down_sync(FULLM, bv, off);
        int   oi = __shfl_down_sync(FULLM, bi, off);
        if (ov > bv || (ov == bv && oi < bi)) { bv = ov; bi = oi; }
    }
    if (lane == 0) {
        float score = __fmul_rn(obj, bv);
        bool  valid = (obj > 0.25f) && (score > 0.25f);
        int b = gw / NP;
        int i = gw - b * NP;
        int cls = bi - 5;
        unsigned inv;
        if (valid) {
            inv = 0x3F800000u - __float_as_uint(score);   // < 0x1000000 when score > 0.25
            atomicAdd(&g_hist[b * 132 + (inv >> 17)], 1);
        } else {
            inv = 0x1000000u;                             // invalid marker
        }
        keys[gw] = (u64)i | ((u64)inv << 15) | ((u64)cls << 40);
    }
}

// ---------------- stage 2: cutoff + ordered compact + 25-bit stable sort + gather ----------------
__global__ void __launch_bounds__(SC_THREADS)
k_sortcompact(const float* __restrict__ pred) {
    typedef cub::BlockRadixSort<unsigned, SC_THREADS, SC_ITEMS, unsigned> BRS;
    __shared__ union {
        struct { unsigned ck[CANDN]; unsigned cv[CANDN]; } c;
        typename BRS::TempStorage sort;
    } u;
    __shared__ int s_wcnt[32], s_woff[32];
    __shared__ int s_base, s_agg, s_cut;
    __shared__ int s_hist[128];

    int b = blockIdx.x, t = threadIdx.x;
    int lane = t & 31, wid = t >> 5;

    if (t < 128) { s_hist[t] = g_hist[b * 132 + t]; g_hist[b * 132 + t] = 0; }
    if (t == 0) s_base = 0;
    __syncthreads();
    if (t == 0) {
        int cum = 0, c = 128;
        for (int i = 0; i < 128; i++) {
            cum += s_hist[i];
            if (cum >= TOPKN) { c = i; break; }
        }
        s_cut = c;
    }
    __syncthreads();
    int cut = s_cut;

    // ordered (idx-ascending) compaction of valid candidates above the cutoff bucket
    for (int r = 0; r < (NP + SC_THREADS - 1) / SC_THREADS; r++) {
        int i = r * SC_THREADS + t;
        u64 key = 0; unsigned inv = 0xFFFFFFFFu;
        bool flag = false;
        if (i < NP) {
            key = g_keys[(size_t)b * NP + i];
            inv = (unsigned)((key >> 15) & 0x1FFFFFFull);
            flag = (inv < 0x1000000u) && ((int)(inv >> 17) <= cut);
        }
        unsigned bal = __ballot_sync(FULLM, flag);
        if (lane == 0) s_wcnt[wid] = __popc(bal);
        __syncthreads();
        if (t < 32) {
            int v = s_wcnt[t], incl = v;
            #pragma unroll
            for (int d = 1; d < 32; d <<= 1) {
                int n = __shfl_up_sync(FULLM, incl, d);
                if (t >= d) incl += n;
            }
            s_woff[t] = incl - v;
            if (t == 31) s_agg = incl;
        }
        __syncthreads();
        if (flag) {
            int pos = s_base + s_woff[wid] + __popc(bal & ((1u << lane) - 1));
            if (pos < CANDN) {
                u.c.ck[pos] = inv;
                u.c.cv[pos] = (unsigned)(key & 0x7FFFull) |
                              ((unsigned)((key >> 40) & 0x7Full) << 16);
            }
        }
        __syncthreads();
        if (t == 0) s_base += s_agg;
    }
    __syncthreads();
    int M = min(s_base, CANDN);

    unsigned keys[SC_ITEMS], vals[SC_ITEMS];
    #pragma unroll
    for (int i = 0; i < SC_ITEMS; i++) {
        int r = t * SC_ITEMS + i;
        keys[i] = (r < M) ? u.c.ck[r] : 0x1FFFFFFu;   // padding sorts last
        vals[i] = (r < M) ? u.c.cv[r] : 0u;
    }
    __syncthreads();
    // stable ascending sort on 25-bit inv; idx-order compaction supplies the tie-break
    BRS(u.sort).Sort(keys, vals, 0, 25);

    #pragma unroll
    for (int i = 0; i < SC_ITEMS; i++) {
        int r = t * SC_ITEMS + i;
        if (r >= TOPKN) continue;
        int g = b * TOPKN + r;
        g_nzflag[g] = 0u;                 // reset sparse flags for this run
        unsigned inv = keys[i];
        if (inv >= 0x1000000u) {          // padding: no real candidate at this rank
            g_boxes[g]   = make_float4(0.f, 0.f, 0.f, 0.f);
            g_shifted[g] = make_float4(0.f, 0.f, 0.f, 0.f);
            g_scores[g]  = 0.f;
            g_clsf[g]    = 0.f;
            continue;
        }
        int idx = (int)(vals[i] & 0xFFFFu);
        int cls = (int)(vals[i] >> 16);
        float s = __uint_as_float(0x3F800000u - inv);

        const float* p = pred + ((size_t)b * NP + idx) * 85;
        float cx = p[0], cy = p[1], w = p[2], h = p[3];
        float x1 = __fsub_rn(cx, __fmul_rn(w, 0.5f));
        float y1 = __fsub_rn(cy, __fmul_rn(h, 0.5f));
        float x2 = __fadd_rn(cx, __fmul_rn(w, 0.5f));
        float y2 = __fadd_rn(cy, __fmul_rn(h, 0.5f));
        float c  = __fmul_rn((float)cls, 4096.0f);

        g_boxes[g]   = make_float4(x1, y1, x2, y2);
        g_shifted[g] = make_float4(__fadd_rn(x1, c), __fadd_rn(y1, c),
                                   __fadd_rn(x2, c), __fadd_rn(y2, c));
        g_scores[g]  = s;
        g_clsf[g]    = (float)cls;
    }
}

// ---------------- stage 3: suppression bitmask + sparsity flags ----------------
__global__ void k_mask() {
    __shared__ float4 cbox[64];
    __shared__ float  carea[64];
    int tI = blockIdx.x, rb = 0, rem = 32;
    while (tI >= rem) { tI -= rem; rb++; rem--; }
    int cb = rb + tI;
    int b = blockIdx.y;
    int tid = threadIdx.x;

    float4 q = g_shifted[(size_t)b * TOPKN + cb * 64 + tid];
    cbox[tid]  = q;
    carea[tid] = __fmul_rn(__fsub_rn(q.z, q.x), __fsub_rn(q.w, q.y));
    __syncthreads();

    int row = rb * 64 + tid;
    float4 a = g_shifted[(size_t)b * TOPKN + row];
    float areaA = __fmul_rn(__fsub_rn(a.z, a.x), __fsub_rn(a.w, a.y));

    u64 bits = 0ull;
    #pragma unroll 8
    for (int j = 0; j < 64; j++) {
        int jg = cb * 64 + j;
        float4 q2 = cbox[j];
        float ltx = fmaxf(a.x, q2.x);
        float lty = fmaxf(a.y, q2.y);
        float rbx = fminf(a.z, q2.z);
        float rby = fminf(a.w, q2.w);
        float ww = fmaxf(__fsub_rn(rbx, ltx), 0.0f);
        float hh = fmaxf(__fsub_rn(rby, lty), 0.0f);
        float inter = __fmul_rn(ww, hh);
        if (jg > row && inter > 0.0f) {
            float denom = __fadd_rn(__fsub_rn(__fadd_rn(areaA, carea[j]), inter), 1e-7f);
            bool bit;
            if (inter > __fmul_rn(0.4501f, denom))       bit = true;
            else if (inter <= __fmul_rn(0.4499f, denom)) bit = false;
            else bit = (__fdiv_rn(inter, denom) > 0.45f);
            if (bit) bits |= (1ull << j);
        }
    }
    if (cb == rb) {
        g_diag[(b * 32 + rb) * 64 + tid] = bits;
    } else {
        g_mask[((size_t)b * TOPKN + rb * 64 + tid) * 32 + cb] = bits;
        if (bits) atomicOr(&g_nzflag[b * TOPKN + row], 1u << cb);
    }
}

// ---------------- stage 4: greedy pass (smem-resident, sparse apply) ----------------
__global__ void __launch_bounds__(256) k_final(float* __restrict__ out) {
    __shared__ u64      s_diag[2048];     // 16 KB: full diagonal
    __shared__ unsigned s_nz[2048];       // 8 KB: row nonzero-word flags
    __shared__ u64      s_valid[32], s_keep[32], s_removed[32];
    __shared__ u64      s_proc;
    __shared__ unsigned s_vb[256];
    __shared__ unsigned s_wbase[32];
    __shared__ unsigned s_total;
    int b = blockIdx.x, t = threadIdx.x;
    int lane = t & 31, wid = t >> 5;

    #pragma unroll
    for (int i = 0; i < 8; i++)
        s_diag[t + 256 * i] = g_diag[b * 2048 + t + 256 * i];
    #pragma unroll
    for (int i = 0; i < 8; i++)
        s_nz[t + 256 * i] = g_nzflag[b * TOPKN + t + 256 * i];
    {   // validity bits: 8 ranks per thread
        const float4* sp = (const float4*)&g_scores[(size_t)b * TOPKN + t * 8];
        float4 A = sp[0], B = sp[1];
        unsigned by = 0;
        by |= (A.x > 0.f) ? 1u : 0; by |= (A.y > 0.f) ? 2u : 0;
        by |= (A.z > 0.f) ? 4u : 0; by |= (A.w > 0.f) ? 8u : 0;
        by |= (B.x > 0.f) ? 16u : 0; by |= (B.y > 0.f) ? 32u : 0;
        by |= (B.z > 0.f) ? 64u : 0; by |= (B.w > 0.f) ? 128u : 0;
        s_vb[t] = by;
    }
    __syncthreads();
    if (t < 32) {
        u64 v = 0ull;
        #pragma unroll
        for (int j = 0; j < 8; j++) v |= (u64)s_vb[t * 8 + j] << (8 * j);
        s_valid[t] = v; s_removed[t] = 0ull; s_keep[t] = 0ull;
    }
    __syncthreads();

    for (int w = 0; w < 32; ++w) {
        if (wid == 0) {
            u64 vw = s_valid[w], rw = s_removed[w];
            u64 c0 = s_diag[w * 64 + lane], c1 = s_diag[w * 64 + lane + 32];
            unsigned nz0 = __ballot_sync(FULLM, c0 != 0ull);
            unsigned nz1 = __ballot_sync(FULLM, c1 != 0ull);
            u64 m = (((u64)nz1 << 32) | (u64)nz0) & vw;
            while (m) {   // serial chain over nonzero suppressor columns only
                int k = __ffsll((long long)m) - 1;
                m &= m - 1;
                if (((vw & ~rw) >> k) & 1ull) rw |= s_diag[w * 64 + k];
            }
            u64 proc = vw & ~rw;
            if (lane == 0) { s_keep[w] = proc; s_proc = proc; }
        }
        __syncthreads();

        // sparse apply: only kept rows with a nonzero word at this lane
        if (lane > w) {
            u64 proc = s_proc;
            u64 acc = 0ull;
            #pragma unroll
            for (int r = 0; r < 8; r++) {
                int k = (r << 3) | wid;
                if (((proc >> k) & 1ull) && ((s_nz[w * 64 + k] >> lane) & 1u))
                    acc |= g_mask[((size_t)b * TOPKN + w * 64 + k) * 32 + lane];
            }
            if (acc) atomicOr(&s_removed[lane], acc);
        }
        __syncthreads();
    }

    // per-word base ranks
    if (wid == 0) {
        unsigned cnt = (unsigned)__popcll(s_keep[lane]), incl = cnt;
        #pragma unroll
        for (int d = 1; d < 32; d <<= 1) {
            unsigned n = __shfl_up_sync(FULLM, incl, d);
            if (lane >= d) incl += n;
        }
        s_wbase[lane] = incl - cnt;
        if (lane == 31) s_total = incl;
    }
    __syncthreads();

    // parallel compaction of survivors (rank order == score order)
    #pragma unroll
    for (int r = 0; r < 8; r++) {
        int gbit = t + 256 * r;
        int word = gbit >> 6, bit = gbit & 63;
        u64 kw = s_keep[word];
        if ((kw >> bit) & 1ull) {
            unsigned rank = s_wbase[word] +
                            (unsigned)__popcll(kw & (((u64)1 << bit) - 1ull));
            if (rank < MAXDET) {
                int g = b * TOPKN + gbit;
                float4 bx = g_boxes[g];
                float* o = out + ((size_t)b * MAXDET + rank) * 6;
                o[0] = bx.x; o[1] = bx.y; o[2] = bx.z; o[3] = bx.w;
                o[4] = g_scores[g];
                o[5] = g_clsf[g];
            }
        }
    }
    unsigned fillstart = min(s_total, (unsigned)MAXDET);
    for (unsigned m = fillstart + t; m < MAXDET; m += 256) {
        float* o = out + ((size_t)b * MAXDET + m) * 6;
        o[0] = 0.f; o[1] = 0.f; o[2] = 0.f; o[3] = 0.f; o[4] = 0.f; o[5] = -1.f;
    }
}

// ---------------- launch ----------------
extern "C" void kernel_launch(void* const* d_in, const int* in_sizes, int n_in,
                              void* d_out, int out_size) {
    (void)in_sizes; (void)n_in; (void)out_size;
    const float* pred = (const float*)d_in[0];
    float* out = (float*)d_out;

    void* keys_p;
    cudaGetSymbolAddress(&keys_p, g_keys);

    {   // stage 1
        int warps = BATCH * NP;
        int threads = 256;
        int blocks = (warps * 32 + threads - 1) / threads;
        k_score<<<blocks, threads>>>(pred, (u64*)keys_p);
    }
    k_sortcompact<<<BATCH, SC_THREADS>>>(pred);
    k_mask<<<dim3(528, BATCH), 64>>>();
    k_final<<<BATCH, 256>>>(out);
}

// round 5
// speedup vs baseline: 2.4125x; 1.1347x over previous
#include <cuda_runtime.h>
#include <cub/cub.cuh>
#include <cstdint>

#define BATCH  16
#define NP     25200
#define TOPKN  2048
#define MAXDET 1000
#define CANDN  3072
#define ECAP   8192
#define SC_THREADS 1024
#define SC_ITEMS   3
#define FULLM  0xffffffffu
typedef unsigned long long u64;

// ---------------- scratch (static device globals) ----------------
__device__ u64      g_keys[BATCH * NP];        // idx(15) | inv(25)<<15 | cls(7)<<40
__device__ int      g_hist[BATCH * 132];       // bucket = inv>>17 (valid only); reset in k_sortcompact
__device__ float4   g_boxes[BATCH * TOPKN];
__device__ float4   g_shifted[BATCH * TOPKN];
__device__ float    g_scores[BATCH * TOPKN];
__device__ float    g_clsf[BATCH * TOPKN];
__device__ int      g_ecnt[BATCH];             // edge counts; reset in k_sortcompact
__device__ unsigned g_edges[BATCH * ECAP];     // packed (i<<16)|j suppression edges, i<j

// ---------------- stage 1: score/class, pack key, bucket histogram ----------------
__global__ void k_score(const float* __restrict__ pred, u64* __restrict__ keys) {
    int gw   = (blockIdx.x * blockDim.x + threadIdx.x) >> 5;
    int lane = threadIdx.x & 31;
    if (gw >= BATCH * NP) return;
    const float* p = pred + (size_t)gw * 85;

    float v0 = p[lane];
    float v1 = p[lane + 32];
    float v2 = (lane < 21) ? p[lane + 64] : -1.0f;
    float obj = __shfl_sync(FULLM, v0, 4);

    float bv = (lane >= 5) ? v0 : -1.0f;
    int   bi = lane;
    if (v1 > bv) { bv = v1; bi = lane + 32; }
    if (v2 > bv) { bv = v2; bi = lane + 64; }
    #pragma unroll
    for (int off = 16; off; off >>= 1) {
        float ov = __shfl_down_sync(FULLM, bv, off);
        int   oi = __shfl_down_sync(FULLM, bi, off);
        if (ov > bv || (ov == bv && oi < bi)) { bv = ov; bi = oi; }
    }
    if (lane == 0) {
        float score = __fmul_rn(obj, bv);
        bool  valid = (obj > 0.25f) && (score > 0.25f);
        int b = gw / NP;
        int i = gw - b * NP;
        int cls = bi - 5;
        unsigned inv;
        if (valid) {
            inv = 0x3F800000u - __float_as_uint(score);   // < 0x1000000 when score > 0.25
            atomicAdd(&g_hist[b * 132 + (inv >> 17)], 1);
        } else {
            inv = 0x1000000u;                             // invalid marker
        }
        keys[gw] = (u64)i | ((u64)inv << 15) | ((u64)cls << 40);
    }
}

// ---------------- stage 2: cutoff + ordered compact + 25-bit stable sort + gather ----------------
__global__ void __launch_bounds__(SC_THREADS)
k_sortcompact(const float* __restrict__ pred) {
    typedef cub::BlockRadixSort<unsigned, SC_THREADS, SC_ITEMS, unsigned> BRS;
    __shared__ union {
        struct { unsigned ck[CANDN]; unsigned cv[CANDN]; } c;
        typename BRS::TempStorage sort;
    } u;
    __shared__ int s_wcnt[32], s_woff[32];
    __shared__ int s_base, s_agg, s_cut;
    __shared__ int s_hist[128];

    int b = blockIdx.x, t = threadIdx.x;
    int lane = t & 31, wid = t >> 5;

    if (t < 128) { s_hist[t] = g_hist[b * 132 + t]; g_hist[b * 132 + t] = 0; }
    if (t == 0) { s_base = 0; g_ecnt[b] = 0; }   // also reset edge counter for k_mask
    __syncthreads();
    if (t == 0) {
        int cum = 0, c = 128;
        for (int i = 0; i < 128; i++) {
            cum += s_hist[i];
            if (cum >= TOPKN) { c = i; break; }
        }
        s_cut = c;
    }
    __syncthreads();
    int cut = s_cut;

    // ordered (idx-ascending) compaction of valid candidates above the cutoff bucket
    for (int r = 0; r < (NP + SC_THREADS - 1) / SC_THREADS; r++) {
        int i = r * SC_THREADS + t;
        u64 key = 0; unsigned inv = 0xFFFFFFFFu;
        bool flag = false;
        if (i < NP) {
            key = g_keys[(size_t)b * NP + i];
            inv = (unsigned)((key >> 15) & 0x1FFFFFFull);
            flag = (inv < 0x1000000u) && ((int)(inv >> 17) <= cut);
        }
        unsigned bal = __ballot_sync(FULLM, flag);
        if (lane == 0) s_wcnt[wid] = __popc(bal);
        __syncthreads();
        if (t < 32) {
            int v = s_wcnt[t], incl = v;
            #pragma unroll
            for (int d = 1; d < 32; d <<= 1) {
                int n = __shfl_up_sync(FULLM, incl, d);
                if (t >= d) incl += n;
            }
            s_woff[t] = incl - v;
            if (t == 31) s_agg = incl;
        }
        __syncthreads();
        if (flag) {
            int pos = s_base + s_woff[wid] + __popc(bal & ((1u << lane) - 1));
            if (pos < CANDN) {
                u.c.ck[pos] = inv;
                u.c.cv[pos] = (unsigned)(key & 0x7FFFull) |
                              ((unsigned)((key >> 40) & 0x7Full) << 16);
            }
        }
        __syncthreads();
        if (t == 0) s_base += s_agg;
    }
    __syncthreads();
    int M = min(s_base, CANDN);

    unsigned keys[SC_ITEMS], vals[SC_ITEMS];
    #pragma unroll
    for (int i = 0; i < SC_ITEMS; i++) {
        int r = t * SC_ITEMS + i;
        keys[i] = (r < M) ? u.c.ck[r] : 0x1FFFFFFu;   // padding sorts last
        vals[i] = (r < M) ? u.c.cv[r] : 0u;
    }
    __syncthreads();
    // stable ascending sort on 25-bit inv; idx-order compaction supplies the tie-break
    BRS(u.sort).Sort(keys, vals, 0, 25);

    #pragma unroll
    for (int i = 0; i < SC_ITEMS; i++) {
        int r = t * SC_ITEMS + i;
        if (r >= TOPKN) continue;
        int g = b * TOPKN + r;
        unsigned inv = keys[i];
        if (inv >= 0x1000000u) {          // padding: no real candidate at this rank
            g_boxes[g]   = make_float4(0.f, 0.f, 0.f, 0.f);
            g_shifted[g] = make_float4(0.f, 0.f, 0.f, 0.f);
            g_scores[g]  = 0.f;
            g_clsf[g]    = 0.f;
            continue;
        }
        int idx = (int)(vals[i] & 0xFFFFu);
        int cls = (int)(vals[i] >> 16);
        float s = __uint_as_float(0x3F800000u - inv);

        const float* p = pred + ((size_t)b * NP + idx) * 85;
        float cx = p[0], cy = p[1], w = p[2], h = p[3];
        float x1 = __fsub_rn(cx, __fmul_rn(w, 0.5f));
        float y1 = __fsub_rn(cy, __fmul_rn(h, 0.5f));
        float x2 = __fadd_rn(cx, __fmul_rn(w, 0.5f));
        float y2 = __fadd_rn(cy, __fmul_rn(h, 0.5f));
        float c  = __fmul_rn((float)cls, 4096.0f);

        g_boxes[g]   = make_float4(x1, y1, x2, y2);
        g_shifted[g] = make_float4(__fadd_rn(x1, c), __fadd_rn(y1, c),
                                   __fadd_rn(x2, c), __fadd_rn(y2, c));
        g_scores[g]  = s;
        g_clsf[g]    = (float)cls;
    }
}

// ---------------- stage 3: IoU -> sparse suppression edges ----------------
__global__ void k_mask() {
    __shared__ float4 cbox[64];
    __shared__ float  carea[64];
    int tI = blockIdx.x, rb = 0, rem = 32;
    while (tI >= rem) { tI -= rem; rb++; rem--; }
    int cb = rb + tI;
    int b = blockIdx.y;
    int tid = threadIdx.x;

    float4 q = g_shifted[(size_t)b * TOPKN + cb * 64 + tid];
    cbox[tid]  = q;
    carea[tid] = __fmul_rn(__fsub_rn(q.z, q.x), __fsub_rn(q.w, q.y));
    __syncthreads();

    int row = rb * 64 + tid;
    float4 a = g_shifted[(size_t)b * TOPKN + row];
    float areaA = __fmul_rn(__fsub_rn(a.z, a.x), __fsub_rn(a.w, a.y));

    u64 bits = 0ull;
    #pragma unroll 8
    for (int j = 0; j < 64; j++) {
        int jg = cb * 64 + j;
        float4 q2 = cbox[j];
        float ltx = fmaxf(a.x, q2.x);
        float lty = fmaxf(a.y, q2.y);
        float rbx = fminf(a.z, q2.z);
        float rby = fminf(a.w, q2.w);
        float ww = fmaxf(__fsub_rn(rbx, ltx), 0.0f);
        float hh = fmaxf(__fsub_rn(rby, lty), 0.0f);
        float inter = __fmul_rn(ww, hh);
        if (jg > row && inter > 0.0f) {
            float denom = __fadd_rn(__fsub_rn(__fadd_rn(areaA, carea[j]), inter), 1e-7f);
            bool bit;
            if (inter > __fmul_rn(0.4501f, denom))       bit = true;
            else if (inter <= __fmul_rn(0.4499f, denom)) bit = false;
            else bit = (__fdiv_rn(inter, denom) > 0.45f);
            if (bit) bits |= (1ull << j);
        }
    }
    // emit sparse edges (rare)
    while (bits) {
        int j = __ffsll((long long)bits) - 1;
        bits &= bits - 1;
        int pos = atomicAdd(&g_ecnt[b], 1);
        if (pos < ECAP)
            g_edges[b * ECAP + pos] = ((unsigned)row << 16) | (unsigned)(cb * 64 + j);
    }
}

// ---------------- stage 4: Jacobi greedy fixpoint + compact output ----------------
__global__ void __launch_bounds__(256) k_final(float* __restrict__ out) {
    __shared__ unsigned s_edges[ECAP];
    __shared__ u64      s_valid[32], s_keep[32], s_sup[32];
    __shared__ unsigned s_vb[256];
    __shared__ unsigned s_wbase[32];
    __shared__ unsigned s_total;
    __shared__ int      s_changed;
    int b = blockIdx.x, t = threadIdx.x;
    int lane = t & 31, wid = t >> 5;

    int E = min(g_ecnt[b], ECAP);
    for (int e = t; e < E; e += 256) s_edges[e] = g_edges[b * ECAP + e];

    {   // validity bits: 8 ranks per thread
        const float4* sp = (const float4*)&g_scores[(size_t)b * TOPKN + t * 8];
        float4 A = sp[0], B = sp[1];
        unsigned by = 0;
        by |= (A.x > 0.f) ? 1u : 0;  by |= (A.y > 0.f) ? 2u : 0;
        by |= (A.z > 0.f) ? 4u : 0;  by |= (A.w > 0.f) ? 8u : 0;
        by |= (B.x > 0.f) ? 16u : 0; by |= (B.y > 0.f) ? 32u : 0;
        by |= (B.z > 0.f) ? 64u : 0; by |= (B.w > 0.f) ? 128u : 0;
        s_vb[t] = by;
    }
    __syncthreads();
    if (t < 32) {
        u64 v = 0ull;
        #pragma unroll
        for (int j = 0; j < 8; j++) v |= (u64)s_vb[t * 8 + j] << (8 * j);
        s_valid[t] = v;
        s_keep[t]  = v;     // optimistic start
    }
    __syncthreads();

    // keep[j] = valid[j] & !exists edge(i,j) with keep[i]; Jacobi to fixpoint.
    // Edges are strictly i<j => DAG; stabilizes in (chain depth + 1) sweeps; a
    // no-change sweep certifies the unique greedy fixpoint.
    int iter_changed;
    do {
        if (t < 32) s_sup[t] = 0ull;
        __syncthreads();                                   // (1)
        for (int e = t; e < E; e += 256) {
            unsigned ed = s_edges[e];
            int i = (int)(ed >> 16), j = (int)(ed & 0xFFFFu);
            if ((s_keep[i >> 6] >> (i & 63)) & 1ull)
                atomicOr(&s_sup[j >> 6], 1ull << (j & 63));
        }
        __syncthreads();                                   // (2)
        if (t == 0) s_changed = 0;
        __syncthreads();                                   // (3)
        if (t < 32) {
            u64 nk = s_valid[t] & ~s_sup[t];
            if (nk != s_keep[t]) { s_keep[t] = nk; s_changed = 1; }
        }
        __syncthreads();                                   // (4)
        iter_changed = s_changed;
    } while (iter_changed);

    // per-word base ranks
    if (wid == 0) {
        unsigned cnt = (unsigned)__popcll(s_keep[lane]), incl = cnt;
        #pragma unroll
        for (int d = 1; d < 32; d <<= 1) {
            unsigned n = __shfl_up_sync(FULLM, incl, d);
            if (lane >= d) incl += n;
        }
        s_wbase[lane] = incl - cnt;
        if (lane == 31) s_total = incl;
    }
    __syncthreads();

    // parallel compaction of survivors (rank order == score order)
    #pragma unroll
    for (int r = 0; r < 8; r++) {
        int gbit = t + 256 * r;
        int word = gbit >> 6, bit = gbit & 63;
        u64 kw = s_keep[word];
        if ((kw >> bit) & 1ull) {
            unsigned rank = s_wbase[word] +
                            (unsigned)__popcll(kw & (((u64)1 << bit) - 1ull));
            if (rank < MAXDET) {
                int g = b * TOPKN + gbit;
                float4 bx = g_boxes[g];
                float* o = out + ((size_t)b * MAXDET + rank) * 6;
                o[0] = bx.x; o[1] = bx.y; o[2] = bx.z; o[3] = bx.w;
                o[4] = g_scores[g];
                o[5] = g_clsf[g];
            }
        }
    }
    unsigned fillstart = min(s_total, (unsigned)MAXDET);
    for (unsigned m = fillstart + t; m < MAXDET; m += 256) {
        float* o = out + ((size_t)b * MAXDET + m) * 6;
        o[0] = 0.f; o[1] = 0.f; o[2] = 0.f; o[3] = 0.f; o[4] = 0.f; o[5] = -1.f;
    }
}

// ---------------- launch ----------------
extern "C" void kernel_launch(void* const* d_in, const int* in_sizes, int n_in,
                              void* d_out, int out_size) {
    (void)in_sizes; (void)n_in; (void)out_size;
    const float* pred = (const float*)d_in[0];
    float* out = (float*)d_out;

    void* keys_p;
    cudaGetSymbolAddress(&keys_p, g_keys);

    {   // stage 1
        int warps = BATCH * NP;
        int threads = 256;
        int blocks = (warps * 32 + threads - 1) / threads;
        k_score<<<blocks, threads>>>(pred, (u64*)keys_p);
    }
    k_sortcompact<<<BATCH, SC_THREADS>>>(pred);
    k_mask<<<dim3(528, BATCH), 64>>>();
    k_final<<<BATCH, 256>>>(out);
}